// round 14
// baseline (speedup 1.0000x reference)
#include <cuda_runtime.h>
#include <cstdint>

#define B_    4
#define H_    8
#define C_    64
#define T_    1024
#define SENC_ 1024

#define NT    256            // 8 warps x 32 queries
#define MQ    256
#define NK    64
#define NTILES 32

#define SCALE_LOG2 0.18033688011112042f   // 0.125 * log2(e), folded into Q

// fp16 K/V scratch: [bh=32][ch=64][keypair=1024] uint32 (2 halves each)
__device__ __align__(16) uint32_t KG[32 * 64 * 1024];
__device__ __align__(16) uint32_t VG[32 * 64 * 1024];

// ---- smem map (bytes): 4 fp16 stages, each K[64][144B] + V[64][144B] ----
#define STG_B  18432u
#define V2REL  9216u
#define QSTG   55296u               // Q fp32 prologue staging reuses stage 3
#define SMEM_BYTES 73728u

static __device__ __forceinline__ uint32_t smem_u32(const void* p) {
    uint32_t a;
    asm("{ .reg .u64 t; cvta.to.shared.u64 t, %1; cvt.u32.u64 %0, t; }" : "=r"(a) : "l"(p));
    return a;
}
static __device__ __forceinline__ uint32_t cvt2h(float hi, float lo) {   // half2{lo,hi}
    uint32_t d; asm("cvt.rn.f16x2.f32 %0, %1, %2;" : "=r"(d) : "f"(hi), "f"(lo)); return d;
}
static __device__ __forceinline__ uint32_t hex2(uint32_t h) {            // exp2 both halves
    uint32_t d; asm("ex2.approx.f16x2 %0, %1;" : "=r"(d) : "r"(h)); return d;
}
static __device__ __forceinline__ void sts32(uint32_t a, uint32_t v) {
    asm volatile("st.shared.b32 [%0], %1;" :: "r"(a), "r"(v) : "memory");
}
static __device__ __forceinline__ float lds32f(uint32_t a) {
    float v; asm volatile("ld.shared.b32 %0, [%1];" : "=f"(v) : "r"(a)); return v;
}
static __device__ __forceinline__ void cp16(uint32_t dst, const void* src) {
    asm volatile("cp.async.cg.shared.global [%0], [%1], 16;" :: "r"(dst), "l"(src) : "memory");
}
#define CP_COMMIT() asm volatile("cp.async.commit_group;" ::: "memory")
#define CP_WAIT2()  asm volatile("cp.async.wait_group 2;" ::: "memory")

#define LDSM4T(r0,r1,r2,r3,a) \
    asm volatile("ldmatrix.sync.aligned.m8n8.x4.trans.shared.b16 {%0,%1,%2,%3}, [%4];" \
        : "=r"(r0), "=r"(r1), "=r"(r2), "=r"(r3) : "r"(a))
#define LDSM4(r0,r1,r2,r3,a) \
    asm volatile("ldmatrix.sync.aligned.m8n8.x4.shared.b16 {%0,%1,%2,%3}, [%4];" \
        : "=r"(r0), "=r"(r1), "=r"(r2), "=r"(r3) : "r"(a))

// D += A*B : m16n8k16 fp16 in, fp32 accum
static __device__ __forceinline__ void mma16(float* c, const uint32_t* a, uint32_t b0, uint32_t b1) {
    asm volatile("mma.sync.aligned.m16n8k16.row.col.f32.f16.f16.f32 "
        "{%0,%1,%2,%3}, {%4,%5,%6,%7}, {%8,%9}, {%0,%1,%2,%3};"
        : "+f"(c[0]), "+f"(c[1]), "+f"(c[2]), "+f"(c[3])
        : "r"(a[0]), "r"(a[1]), "r"(a[2]), "r"(a[3]), "r"(b0), "r"(b1));
}

// ---------- prep: fp32 K/V (x + encoder_kv) -> fp16 KG/VG ----------
__global__ void __launch_bounds__(256)
prep_kernel(const float* __restrict__ x, const float* __restrict__ ekv)
{
    int g   = blockIdx.x * 256 + threadIdx.x;   // 2^21 threads
    int sp4 = g & 511;                          // 4 keys per thread
    int ch  = (g >> 9) & 63;
    int bh  = (g >> 15) & 31;
    int m   = g >> 20;                          // 0=K 1=V
    int b   = bh >> 3, h = bh & 7;
    int s0  = sp4 * 4;

    const float* src;
    if (s0 < SENC_)
        src = ekv + ((size_t)(b * 1024 + m * 512 + h * 64 + ch)) * SENC_ + s0;
    else
        src = x + ((size_t)(b * 1536 + (m + 1) * 512 + h * 64 + ch)) * T_ + (s0 - SENC_);

    float4 a = *(const float4*)src;
    uint32_t* dst = (m ? VG : KG) + ((size_t)bh * 64 + ch) * 1024 + (s0 >> 1);
    uint2 o = make_uint2(cvt2h(a.y, a.x), cvt2h(a.w, a.z));
    *(uint2*)dst = o;
}

// ---------- main attention: deferred-exp pipeline, 1 CTA/SM ----------
__global__ void __launch_bounds__(NT, 1)
attn_dx_kernel(const float* __restrict__ x, float* __restrict__ out)
{
    extern __shared__ float smraw[];
    const uint32_t SB = smem_u32(smraw);

    const int tid = threadIdx.x;
    const int wid = tid >> 5;
    const int lid = tid & 31;
    const int lg  = lid >> 2;
    const int l4  = lid & 3;
    const int m0  = wid * 32;                    // warp query base (0..224)

    const int qt = blockIdx.x;                   // 0..3
    const int bh = blockIdx.y;
    const int b  = bh >> 3;
    const int h  = bh & 7;
    const int q0 = qt * MQ;

    const float* qp = x + ((size_t)b * 3 * H_ * C_ + h * C_) * T_;
    float* op = out + ((size_t)b * H_ * C_ + h * C_) * T_;
    const uint32_t* KGp = KG + (size_t)bh * 65536;
    const uint32_t* VGp = VG + (size_t)bh * 65536;

    // ---- prologue: cp.async fp16 tiles 0,1 into stages 0,1 ----
    #pragma unroll
    for (int pf = 0; pf < 2; pf++) {
        uint32_t st = SB + (uint32_t)pf * STG_B;
        #pragma unroll
        for (int it = 0; it < 4; it++) {
            int idx = tid + it * NT;                 // 1024 chunks
            int m   = idx >> 9;
            int ch  = (idx >> 3) & 63;
            int c8  = idx & 7;
            const uint32_t* src = (m ? VGp : KGp) + ch * 1024 + pf * 32 + c8 * 4;
            cp16(st + (uint32_t)m * V2REL + (uint32_t)ch * 144u + (uint32_t)c8 * 16u, src);
        }
        CP_COMMIT();
    }

    // ---- stage Q (four 64-query fp32 passes through stage-3 area) ----
    uint32_t qa[2][4][4];
    #pragma unroll
    for (int p = 0; p < 4; p++) {
        #pragma unroll
        for (int it = 0; it < 4; it++) {
            int idx = tid + it * NT;                 // 1024 float4s = 64q x 64ch
            int ch  = idx >> 4;
            int q4  = (idx & 15) << 2;
            float4 v = *(const float4*)(qp + (size_t)ch * T_ + q0 + p * 64 + q4);
            uint32_t base = SB + QSTG + (uint32_t)ch * 4u;
            sts32(base + (uint32_t)(q4 + 0) * 272u, __float_as_uint(v.x));
            sts32(base + (uint32_t)(q4 + 1) * 272u, __float_as_uint(v.y));
            sts32(base + (uint32_t)(q4 + 2) * 272u, __float_as_uint(v.z));
            sts32(base + (uint32_t)(q4 + 3) * 272u, __float_as_uint(v.w));
        }
        __syncthreads();
        if ((wid >> 1) == p) {                       // warps 2p, 2p+1 extract
            int rbase = m0 - p * 64;
            #pragma unroll
            for (int mb = 0; mb < 2; mb++)
                #pragma unroll
                for (int kc = 0; kc < 4; kc++)
                    #pragma unroll
                    for (int j = 0; j < 4; j++) {
                        int r = rbase + 16 * mb + lg + 8 * (j & 1);
                        int c = kc * 8 + l4 + 4 * (j >> 1);
                        float f0 = lds32f(SB + QSTG + ((uint32_t)r * 68u + (uint32_t)(2 * c)) * 4u);
                        float f1 = lds32f(SB + QSTG + ((uint32_t)r * 68u + (uint32_t)(2 * c + 1)) * 4u);
                        qa[mb][kc][j] = cvt2h(f1 * SCALE_LOG2, f0 * SCALE_LOG2);
                    }
        }
        __syncthreads();
    }

    float oc[2][8][4];
    float ol[2][4];
    #pragma unroll
    for (int mb = 0; mb < 2; mb++) {
        #pragma unroll
        for (int e = 0; e < 4; e++) ol[mb][e] = 0.f;
        #pragma unroll
        for (int nc = 0; nc < 8; nc++)
            #pragma unroll
            for (int e = 0; e < 4; e++) oc[mb][nc][e] = 0.f;
    }

    // constant B-fragment for the ones-channel lsum GEMM (n==0 row of ones)
    const uint32_t lones = (lg == 0) ? 0x3C003C00u : 0u;

    // per-thread ldmatrix offsets within a stage
    const int jm = lid >> 3;
    const int rr = lid & 7;
    const uint32_t kof = (uint32_t)((8 * (jm & 1) + rr) * 144 + (jm >> 1) * 16);
    const uint32_t vof = V2REL + (uint32_t)(((jm >> 1) * 8 + rr) * 144 + (jm & 1) * 16);

    uint32_t pa[2][4][4];                        // P fragments of tile kt-1

    #pragma unroll 1
    for (int kt = 0; kt < NTILES; kt++) {
        // cp.async tile kt+2 -> stage (kt+2)&3 (free: tile kt-2 fully consumed)
        {
            int nt = kt + 2;
            if (nt < NTILES) {
                uint32_t st = SB + (uint32_t)(nt & 3) * STG_B;
                #pragma unroll
                for (int it = 0; it < 4; it++) {
                    int idx = tid + it * NT;
                    int m   = idx >> 9;
                    int ch  = (idx >> 3) & 63;
                    int c8  = idx & 7;
                    const uint32_t* src = (m ? VGp : KGp) + ch * 1024 + nt * 32 + c8 * 4;
                    cp16(st + (uint32_t)m * V2REL + (uint32_t)ch * 144u + (uint32_t)c8 * 16u, src);
                }
            }
            CP_COMMIT();
        }
        CP_WAIT2();                    // tile kt landed (2 newer groups in flight)
        __syncthreads();               // visible to all; fences stage reuse AND orders
                                       // everyone past PV(kt-2) before its stage refill

        const uint32_t kbase = SB + (uint32_t)(kt & 3) * STG_B + kof;

        // ---- S = Q K^T (tile kt) ----
        float sc[2][8][4];
        #pragma unroll
        for (int mb = 0; mb < 2; mb++)
            #pragma unroll
            for (int nc = 0; nc < 8; nc++)
                #pragma unroll
                for (int e = 0; e < 4; e++) sc[mb][nc][e] = 0.f;

        #pragma unroll
        for (int ncp = 0; ncp < 4; ncp++) {
            #pragma unroll
            for (int kc = 0; kc < 4; kc++) {
                uint32_t f0, f1, f2, f3;
                LDSM4T(f0, f1, f2, f3, kbase + (uint32_t)(kc * 2304 + ncp * 32));
                mma16(sc[0][2 * ncp],     qa[0][kc], f0, f1);
                mma16(sc[1][2 * ncp],     qa[1][kc], f0, f1);
                mma16(sc[0][2 * ncp + 1], qa[0][kc], f2, f3);
                mma16(sc[1][2 * ncp + 1], qa[1][kc], f2, f3);
            }
        }

        // ---- O += P V^T (tile kt-1) — contiguous with QK on the tensor pipe ----
        if (kt > 0) {
            const uint32_t vbase = SB + (uint32_t)((kt - 1) & 3) * STG_B + vof;
            #pragma unroll
            for (int ncp = 0; ncp < 4; ncp++) {
                #pragma unroll
                for (int kc = 0; kc < 4; kc++) {
                    uint32_t f0, f1, f2, f3;
                    LDSM4(f0, f1, f2, f3, vbase + (uint32_t)(ncp * 2304 + kc * 32));
                    mma16(oc[0][2 * ncp],     pa[0][kc], f0, f1);
                    mma16(oc[1][2 * ncp],     pa[1][kc], f0, f1);
                    mma16(oc[0][2 * ncp + 1], pa[0][kc], f2, f3);
                    mma16(oc[1][2 * ncp + 1], pa[1][kc], f2, f3);
                }
            }
            #pragma unroll
            for (int kc = 0; kc < 4; kc++) {
                mma16(ol[0], pa[0][kc], lones, lones);
                mma16(ol[1], pa[1][kc], lones, lones);
            }
        }

        // ---- exp (tile kt) -> pa; overlaps next iteration's barrier/copy ----
        #pragma unroll
        for (int mb = 0; mb < 2; mb++) {
            #pragma unroll
            for (int kc = 0; kc < 4; kc++) {
                pa[mb][kc][0] = hex2(cvt2h(sc[mb][2 * kc][1],     sc[mb][2 * kc][0]));
                pa[mb][kc][1] = hex2(cvt2h(sc[mb][2 * kc][3],     sc[mb][2 * kc][2]));
                pa[mb][kc][2] = hex2(cvt2h(sc[mb][2 * kc + 1][1], sc[mb][2 * kc + 1][0]));
                pa[mb][kc][3] = hex2(cvt2h(sc[mb][2 * kc + 1][3], sc[mb][2 * kc + 1][2]));
            }
        }
    }

    // ---- tail: PV of the last tile (stage 31&3 = 3, untouched after loop) ----
    {
        const uint32_t vbase = SB + (uint32_t)((NTILES - 1) & 3) * STG_B + vof;
        #pragma unroll
        for (int ncp = 0; ncp < 4; ncp++) {
            #pragma unroll
            for (int kc = 0; kc < 4; kc++) {
                uint32_t f0, f1, f2, f3;
                LDSM4(f0, f1, f2, f3, vbase + (uint32_t)(ncp * 2304 + kc * 32));
                mma16(oc[0][2 * ncp],     pa[0][kc], f0, f1);
                mma16(oc[1][2 * ncp],     pa[1][kc], f0, f1);
                mma16(oc[0][2 * ncp + 1], pa[0][kc], f2, f3);
                mma16(oc[1][2 * ncp + 1], pa[1][kc], f2, f3);
            }
        }
        #pragma unroll
        for (int kc = 0; kc < 4; kc++) {
            mma16(ol[0], pa[0][kc], lones, lones);
            mma16(ol[1], pa[1][kc], lones, lones);
        }
    }

    // ---- epilogue: quad-XOR spreads lsum (non-leader lanes hold 0) ----
    float inv[2][2];
    #pragma unroll
    for (int mb = 0; mb < 2; mb++) {
        float v0 = ol[mb][0];
        float v1 = ol[mb][2];
        v0 += __shfl_xor_sync(0xffffffffu, v0, 1);
        v0 += __shfl_xor_sync(0xffffffffu, v0, 2);
        v1 += __shfl_xor_sync(0xffffffffu, v1, 1);
        v1 += __shfl_xor_sync(0xffffffffu, v1, 2);
        inv[mb][0] = 1.0f / v0;
        inv[mb][1] = 1.0f / v1;
    }

    #pragma unroll
    for (int mb = 0; mb < 2; mb++) {
        int q = q0 + m0 + 16 * mb + lg;
        #pragma unroll
        for (int nc = 0; nc < 8; nc++) {
            int ch = 8 * nc + 2 * l4;
            op[(size_t)ch       * T_ + q]     = oc[mb][nc][0] * inv[mb][0];
            op[(size_t)(ch + 1) * T_ + q]     = oc[mb][nc][1] * inv[mb][0];
            op[(size_t)ch       * T_ + q + 8] = oc[mb][nc][2] * inv[mb][1];
            op[(size_t)(ch + 1) * T_ + q + 8] = oc[mb][nc][3] * inv[mb][1];
        }
    }
}

extern "C" void kernel_launch(void* const* d_in, const int* in_sizes, int n_in,
                              void* d_out, int out_size)
{
    const float* x   = (const float*)d_in[0];   // (4, 1536, 1024)
    const float* ekv = (const float*)d_in[1];   // (4, 1024, 1024)
    float* out = (float*)d_out;                 // (4, 512, 1024)

    prep_kernel<<<8192, 256>>>(x, ekv);

    cudaFuncSetAttribute(attn_dx_kernel, cudaFuncAttributeMaxDynamicSharedMemorySize, SMEM_BYTES);
    dim3 grid(T_ / MQ, B_ * H_);                // (4, 32) = 128 CTAs, 1/SM, one wave
    attn_dx_kernel<<<grid, NT, SMEM_BYTES>>>(x, out);
}

// round 15
// speedup vs baseline: 1.1101x; 1.1101x over previous
#include <cuda_runtime.h>
#include <cstdint>

#define B_    4
#define H_    8
#define C_    64
#define T_    1024
#define SENC_ 1024

#define NT    256            // 8 warps x 32 queries
#define MQ    256
#define NK    64
#define NTILES 32

#define SCALE_LOG2 0.18033688011112042f   // 0.125 * log2(e), folded into Q

// fp16 K/V scratch: [bh=32][ch=64][keypair=1024] uint32 (2 halves each)
__device__ __align__(16) uint32_t KG[32 * 64 * 1024];
__device__ __align__(16) uint32_t VG[32 * 64 * 1024];

// ---- smem map (bytes): 4 fp16 stages, each K[64][144B] + V[64][144B] ----
#define STG_B  18432u
#define V2REL  9216u
#define SMEM_BYTES 73728u

static __device__ __forceinline__ uint32_t smem_u32(const void* p) {
    uint32_t a;
    asm("{ .reg .u64 t; cvta.to.shared.u64 t, %1; cvt.u32.u64 %0, t; }" : "=r"(a) : "l"(p));
    return a;
}
static __device__ __forceinline__ uint32_t cvt2h(float hi, float lo) {   // half2{lo,hi}
    uint32_t d; asm("cvt.rn.f16x2.f32 %0, %1, %2;" : "=r"(d) : "f"(hi), "f"(lo)); return d;
}
static __device__ __forceinline__ uint32_t hex2(uint32_t h) {            // exp2 both halves
    uint32_t d; asm("ex2.approx.f16x2 %0, %1;" : "=r"(d) : "r"(h)); return d;
}
static __device__ __forceinline__ uint32_t hadd2(uint32_t a, uint32_t b) {
    uint32_t d; asm("add.f16x2 %0, %1, %2;" : "=r"(d) : "r"(a), "r"(b)); return d;
}
static __device__ __forceinline__ float h2sum(uint32_t h) {              // lo+hi as fp32
    float lo, hi;
    asm("{ .reg .f16 l, u; mov.b32 {l,u}, %2; cvt.f32.f16 %0, l; cvt.f32.f16 %1, u; }"
        : "=f"(lo), "=f"(hi) : "r"(h));
    return lo + hi;
}
static __device__ __forceinline__ void cp16(uint32_t dst, const void* src) {
    asm volatile("cp.async.cg.shared.global [%0], [%1], 16;" :: "r"(dst), "l"(src) : "memory");
}
#define CP_COMMIT() asm volatile("cp.async.commit_group;" ::: "memory")
#define CP_WAIT2()  asm volatile("cp.async.wait_group 2;" ::: "memory")

#define LDSM4T(r0,r1,r2,r3,a) \
    asm volatile("ldmatrix.sync.aligned.m8n8.x4.trans.shared.b16 {%0,%1,%2,%3}, [%4];" \
        : "=r"(r0), "=r"(r1), "=r"(r2), "=r"(r3) : "r"(a))
#define LDSM4(r0,r1,r2,r3,a) \
    asm volatile("ldmatrix.sync.aligned.m8n8.x4.shared.b16 {%0,%1,%2,%3}, [%4];" \
        : "=r"(r0), "=r"(r1), "=r"(r2), "=r"(r3) : "r"(a))

// D += A*B : m16n8k16 fp16 in, fp32 accum
static __device__ __forceinline__ void mma16(float* c, const uint32_t* a, uint32_t b0, uint32_t b1) {
    asm volatile("mma.sync.aligned.m16n8k16.row.col.f32.f16.f16.f32 "
        "{%0,%1,%2,%3}, {%4,%5,%6,%7}, {%8,%9}, {%0,%1,%2,%3};"
        : "+f"(c[0]), "+f"(c[1]), "+f"(c[2]), "+f"(c[3])
        : "r"(a[0]), "r"(a[1]), "r"(a[2]), "r"(a[3]), "r"(b0), "r"(b1));
}

// ---------- prep: fp32 K/V (x + encoder_kv) -> fp16 KG/VG ----------
__global__ void __launch_bounds__(256)
prep_kernel(const float* __restrict__ x, const float* __restrict__ ekv)
{
    int g   = blockIdx.x * 256 + threadIdx.x;   // 2^21 threads
    int sp4 = g & 511;                          // 4 keys per thread
    int ch  = (g >> 9) & 63;
    int bh  = (g >> 15) & 31;
    int m   = g >> 20;                          // 0=K 1=V
    int b   = bh >> 3, h = bh & 7;
    int s0  = sp4 * 4;

    const float* src;
    if (s0 < SENC_)
        src = ekv + ((size_t)(b * 1024 + m * 512 + h * 64 + ch)) * SENC_ + s0;
    else
        src = x + ((size_t)(b * 1536 + (m + 1) * 512 + h * 64 + ch)) * T_ + (s0 - SENC_);

    float4 a = *(const float4*)src;
    uint32_t* dst = (m ? VG : KG) + ((size_t)bh * 64 + ch) * 1024 + (s0 >> 1);
    uint2 o = make_uint2(cvt2h(a.y, a.x), cvt2h(a.w, a.z));
    *(uint2*)dst = o;
}

// ---------- main attention kernel: one CTA per SM, 8 warps x 32 queries ----------
__global__ void __launch_bounds__(NT, 1)
attn_r15_kernel(const float* __restrict__ x, float* __restrict__ out)
{
    extern __shared__ float smraw[];
    const uint32_t SB = smem_u32(smraw);

    const int tid = threadIdx.x;
    const int wid = tid >> 5;
    const int lid = tid & 31;
    const int lg  = lid >> 2;
    const int l4  = lid & 3;
    const int m0  = wid * 32;                    // warp query base (0..224)

    const int qt = blockIdx.x;                   // 0..3
    const int bh = blockIdx.y;
    const int b  = bh >> 3;
    const int h  = bh & 7;
    const int q0 = qt * MQ;

    const float* qp = x + ((size_t)b * 3 * H_ * C_ + h * C_) * T_;
    float* op = out + ((size_t)b * H_ * C_ + h * C_) * T_;
    const uint32_t* KGp = KG + (size_t)bh * 65536;
    const uint32_t* VGp = VG + (size_t)bh * 65536;

    // ---- prologue: cp.async fp16 tiles 0,1 into stages 0,1 ----
    #pragma unroll
    for (int pf = 0; pf < 2; pf++) {
        uint32_t st = SB + (uint32_t)pf * STG_B;
        #pragma unroll
        for (int it = 0; it < 4; it++) {
            int idx = tid + it * NT;                 // 1024 chunks
            int m   = idx >> 9;
            int ch  = (idx >> 3) & 63;
            int c8  = idx & 7;
            const uint32_t* src = (m ? VGp : KGp) + ch * 1024 + pf * 32 + c8 * 4;
            cp16(st + (uint32_t)m * V2REL + (uint32_t)ch * 144u + (uint32_t)c8 * 16u, src);
        }
        CP_COMMIT();
    }

    // ---- Q fragments straight from gmem (contiguous 32B sectors per quad) ----
    uint32_t qa[2][4][4];
    #pragma unroll
    for (int mb = 0; mb < 2; mb++)
        #pragma unroll
        for (int kc = 0; kc < 4; kc++)
            #pragma unroll
            for (int j = 0; j < 4; j++) {
                int q = q0 + m0 + 16 * mb + lg + 8 * (j & 1);
                int c = kc * 8 + l4 + 4 * (j >> 1);          // channel-pair index
                const float* p = qp + (size_t)(2 * c) * T_ + q;
                float f0 = __ldg(p);
                float f1 = __ldg(p + T_);
                qa[mb][kc][j] = cvt2h(f1 * SCALE_LOG2, f0 * SCALE_LOG2);
            }

    float oc[2][8][4];
    float lsa[2][2] = {{0.f, 0.f}, {0.f, 0.f}};  // fp32 lsum partials (16 keys each)
    #pragma unroll
    for (int mb = 0; mb < 2; mb++)
        #pragma unroll
        for (int nc = 0; nc < 8; nc++)
            #pragma unroll
            for (int e = 0; e < 4; e++) oc[mb][nc][e] = 0.f;

    // per-thread ldmatrix offsets within a stage
    const int jm = lid >> 3;
    const int rr = lid & 7;
    const uint32_t kof = (uint32_t)((8 * (jm & 1) + rr) * 144 + (jm >> 1) * 16);
    const uint32_t vof = V2REL + (uint32_t)(((jm >> 1) * 8 + rr) * 144 + (jm & 1) * 16);

    #pragma unroll 1
    for (int kt = 0; kt < NTILES; kt++) {
        // cp.async tile kt+2 -> stage (kt+2)&3 (free since tile kt-2 finished)
        {
            int nt = kt + 2;
            if (nt < NTILES) {
                uint32_t st = SB + (uint32_t)(nt & 3) * STG_B;
                #pragma unroll
                for (int it = 0; it < 4; it++) {
                    int idx = tid + it * NT;
                    int m   = idx >> 9;
                    int ch  = (idx >> 3) & 63;
                    int c8  = idx & 7;
                    const uint32_t* src = (m ? VGp : KGp) + ch * 1024 + nt * 32 + c8 * 4;
                    cp16(st + (uint32_t)m * V2REL + (uint32_t)ch * 144u + (uint32_t)c8 * 16u, src);
                }
            }
            CP_COMMIT();
        }
        CP_WAIT2();                    // tile kt landed (2 newer groups in flight)
        __syncthreads();               // visible to all; also fences stage reuse

        const uint32_t fb    = SB + (uint32_t)(kt & 3) * STG_B;
        const uint32_t kbase = fb + kof;
        const uint32_t vbase = fb + vof;

        // ---- S = Q K^T ----
        float sc[2][8][4];
        #pragma unroll
        for (int mb = 0; mb < 2; mb++)
            #pragma unroll
            for (int nc = 0; nc < 8; nc++)
                #pragma unroll
                for (int e = 0; e < 4; e++) sc[mb][nc][e] = 0.f;

        #pragma unroll
        for (int ncp = 0; ncp < 4; ncp++) {
            #pragma unroll
            for (int kc = 0; kc < 4; kc++) {
                uint32_t f0, f1, f2, f3;
                LDSM4T(f0, f1, f2, f3, kbase + (uint32_t)(kc * 2304 + ncp * 32));
                mma16(sc[0][2 * ncp],     qa[0][kc], f0, f1);
                mma16(sc[1][2 * ncp],     qa[1][kc], f0, f1);
                mma16(sc[0][2 * ncp + 1], qa[0][kc], f2, f3);
                mma16(sc[1][2 * ncp + 1], qa[1][kc], f2, f3);
            }
        }

        // ---- softmax: pack logits to f16x2, exp2 both halves -> A fragments ----
        uint32_t pa[2][4][4];
        #pragma unroll
        for (int mb = 0; mb < 2; mb++) {
            #pragma unroll
            for (int kc = 0; kc < 4; kc++) {
                pa[mb][kc][0] = hex2(cvt2h(sc[mb][2 * kc][1],     sc[mb][2 * kc][0]));
                pa[mb][kc][1] = hex2(cvt2h(sc[mb][2 * kc][3],     sc[mb][2 * kc][2]));
                pa[mb][kc][2] = hex2(cvt2h(sc[mb][2 * kc + 1][1], sc[mb][2 * kc + 1][0]));
                pa[mb][kc][3] = hex2(cvt2h(sc[mb][2 * kc + 1][3], sc[mb][2 * kc + 1][2]));
            }
        }

        // ---- lsum via f16x2 adder tree (FMA pipe; tensor pipe freed) ----
        #pragma unroll
        for (int mb = 0; mb < 2; mb++) {
            uint32_t r0 = hadd2(hadd2(pa[mb][0][0], pa[mb][1][0]),
                                hadd2(pa[mb][2][0], pa[mb][3][0]));
            uint32_t r2 = hadd2(hadd2(pa[mb][0][2], pa[mb][1][2]),
                                hadd2(pa[mb][2][2], pa[mb][3][2]));
            lsa[mb][0] += h2sum(hadd2(r0, r2));                 // row lg
            uint32_t r1 = hadd2(hadd2(pa[mb][0][1], pa[mb][1][1]),
                                hadd2(pa[mb][2][1], pa[mb][3][1]));
            uint32_t r3 = hadd2(hadd2(pa[mb][0][3], pa[mb][1][3]),
                                hadd2(pa[mb][2][3], pa[mb][3][3]));
            lsa[mb][1] += h2sum(hadd2(r1, r3));                 // row lg+8
        }

        // ---- O += P V^T ----
        #pragma unroll
        for (int ncp = 0; ncp < 4; ncp++) {
            #pragma unroll
            for (int kc = 0; kc < 4; kc++) {
                uint32_t f0, f1, f2, f3;
                LDSM4(f0, f1, f2, f3, vbase + (uint32_t)(ncp * 2304 + kc * 32));
                mma16(oc[0][2 * ncp],     pa[0][kc], f0, f1);
                mma16(oc[1][2 * ncp],     pa[1][kc], f0, f1);
                mma16(oc[0][2 * ncp + 1], pa[0][kc], f2, f3);
                mma16(oc[1][2 * ncp + 1], pa[1][kc], f2, f3);
            }
        }
    }

    // ---- epilogue: quad-XOR reduces lsum over l4 lanes ----
    float inv[2][2];
    #pragma unroll
    for (int mb = 0; mb < 2; mb++) {
        float v0 = lsa[mb][0];
        float v1 = lsa[mb][1];
        v0 += __shfl_xor_sync(0xffffffffu, v0, 1);
        v0 += __shfl_xor_sync(0xffffffffu, v0, 2);
        v1 += __shfl_xor_sync(0xffffffffu, v1, 1);
        v1 += __shfl_xor_sync(0xffffffffu, v1, 2);
        inv[mb][0] = 1.0f / v0;
        inv[mb][1] = 1.0f / v1;
    }

    #pragma unroll
    for (int mb = 0; mb < 2; mb++) {
        int q = q0 + m0 + 16 * mb + lg;
        #pragma unroll
        for (int nc = 0; nc < 8; nc++) {
            int ch = 8 * nc + 2 * l4;
            op[(size_t)ch       * T_ + q]     = oc[mb][nc][0] * inv[mb][0];
            op[(size_t)(ch + 1) * T_ + q]     = oc[mb][nc][1] * inv[mb][0];
            op[(size_t)ch       * T_ + q + 8] = oc[mb][nc][2] * inv[mb][1];
            op[(size_t)(ch + 1) * T_ + q + 8] = oc[mb][nc][3] * inv[mb][1];
        }
    }
}

extern "C" void kernel_launch(void* const* d_in, const int* in_sizes, int n_in,
                              void* d_out, int out_size)
{
    const float* x   = (const float*)d_in[0];   // (4, 1536, 1024)
    const float* ekv = (const float*)d_in[1];   // (4, 1024, 1024)
    float* out = (float*)d_out;                 // (4, 512, 1024)

    prep_kernel<<<8192, 256>>>(x, ekv);

    cudaFuncSetAttribute(attn_r15_kernel, cudaFuncAttributeMaxDynamicSharedMemorySize, SMEM_BYTES);
    dim3 grid(T_ / MQ, B_ * H_);                // (4, 32) = 128 CTAs, 1/SM, one wave
    attn_r15_kernel<<<grid, NT, SMEM_BYTES>>>(x, out);
}

// round 16
// speedup vs baseline: 1.1107x; 1.0006x over previous
#include <cuda_runtime.h>
#include <cstdint>

#define B_    4
#define H_    8
#define C_    64
#define T_    1024
#define SENC_ 1024

#define NT    256            // 8 warps x 32 queries
#define MQ    256
#define NK    64
#define NTILES 32

#define SCALE_LOG2 0.18033688011112042f   // 0.125 * log2(e), folded into Q

// fp16 K/V scratch: [bh=32][ch=64][keypair=1024] uint32 (2 halves each)
__device__ __align__(16) uint32_t KG[32 * 64 * 1024];
__device__ __align__(16) uint32_t VG[32 * 64 * 1024];

// ---- smem map (bytes): 6 fp16 stages, each K[64][144B] + V[64][144B] ----
#define STG_B  18432u
#define V2REL  9216u
#define SMEM_BYTES 110592u          // 6 stages, 1 CTA/SM

static __device__ __forceinline__ uint32_t smem_u32(const void* p) {
    uint32_t a;
    asm("{ .reg .u64 t; cvta.to.shared.u64 t, %1; cvt.u32.u64 %0, t; }" : "=r"(a) : "l"(p));
    return a;
}
static __device__ __forceinline__ uint32_t cvt2h(float hi, float lo) {   // half2{lo,hi}
    uint32_t d; asm("cvt.rn.f16x2.f32 %0, %1, %2;" : "=r"(d) : "f"(hi), "f"(lo)); return d;
}
static __device__ __forceinline__ uint32_t hex2(uint32_t h) {            // exp2 both halves
    uint32_t d; asm("ex2.approx.f16x2 %0, %1;" : "=r"(d) : "r"(h)); return d;
}
static __device__ __forceinline__ uint32_t hadd2(uint32_t a, uint32_t b) {
    uint32_t d; asm("add.f16x2 %0, %1, %2;" : "=r"(d) : "r"(a), "r"(b)); return d;
}
static __device__ __forceinline__ float h2sum(uint32_t h) {              // lo+hi as fp32
    float lo, hi;
    asm("{ .reg .f16 l, u; mov.b32 {l,u}, %2; cvt.f32.f16 %0, l; cvt.f32.f16 %1, u; }"
        : "=f"(lo), "=f"(hi) : "r"(h));
    return lo + hi;
}
static __device__ __forceinline__ void cp16(uint32_t dst, const void* src) {
    asm volatile("cp.async.cg.shared.global [%0], [%1], 16;" :: "r"(dst), "l"(src) : "memory");
}
#define CP_COMMIT() asm volatile("cp.async.commit_group;" ::: "memory")
#define CP_WAIT2()  asm volatile("cp.async.wait_group 2;" ::: "memory")

#define LDSM4T(r0,r1,r2,r3,a) \
    asm volatile("ldmatrix.sync.aligned.m8n8.x4.trans.shared.b16 {%0,%1,%2,%3}, [%4];" \
        : "=r"(r0), "=r"(r1), "=r"(r2), "=r"(r3) : "r"(a))
#define LDSM4(r0,r1,r2,r3,a) \
    asm volatile("ldmatrix.sync.aligned.m8n8.x4.shared.b16 {%0,%1,%2,%3}, [%4];" \
        : "=r"(r0), "=r"(r1), "=r"(r2), "=r"(r3) : "r"(a))

// D += A*B : m16n8k16 fp16 in, fp32 accum
static __device__ __forceinline__ void mma16(float* c, const uint32_t* a, uint32_t b0, uint32_t b1) {
    asm volatile("mma.sync.aligned.m16n8k16.row.col.f32.f16.f16.f32 "
        "{%0,%1,%2,%3}, {%4,%5,%6,%7}, {%8,%9}, {%0,%1,%2,%3};"
        : "+f"(c[0]), "+f"(c[1]), "+f"(c[2]), "+f"(c[3])
        : "r"(a[0]), "r"(a[1]), "r"(a[2]), "r"(a[3]), "r"(b0), "r"(b1));
}

// ---------- prep: fp32 K/V (x + encoder_kv) -> fp16 KG/VG ----------
__global__ void __launch_bounds__(256)
prep_kernel(const float* __restrict__ x, const float* __restrict__ ekv)
{
    int g   = blockIdx.x * 256 + threadIdx.x;   // 2^21 threads
    int sp4 = g & 511;                          // 4 keys per thread
    int ch  = (g >> 9) & 63;
    int bh  = (g >> 15) & 31;
    int m   = g >> 20;                          // 0=K 1=V
    int b   = bh >> 3, h = bh & 7;
    int s0  = sp4 * 4;

    const float* src;
    if (s0 < SENC_)
        src = ekv + ((size_t)(b * 1024 + m * 512 + h * 64 + ch)) * SENC_ + s0;
    else
        src = x + ((size_t)(b * 1536 + (m + 1) * 512 + h * 64 + ch)) * T_ + (s0 - SENC_);

    float4 a = *(const float4*)src;
    uint32_t* dst = (m ? VG : KG) + ((size_t)bh * 64 + ch) * 1024 + (s0 >> 1);
    uint2 o = make_uint2(cvt2h(a.y, a.x), cvt2h(a.w, a.z));
    *(uint2*)dst = o;
}

// ---------- main attention kernel: 1 CTA/SM, barrier per tile-pair ----------
__global__ void __launch_bounds__(NT, 1)
attn_r16_kernel(const float* __restrict__ x, float* __restrict__ out)
{
    extern __shared__ float smraw[];
    const uint32_t SB = smem_u32(smraw);

    const int tid = threadIdx.x;
    const int wid = tid >> 5;
    const int lid = tid & 31;
    const int lg  = lid >> 2;
    const int l4  = lid & 3;
    const int m0  = wid * 32;                    // warp query base (0..224)

    const int qt = blockIdx.x;                   // 0..3
    const int bh = blockIdx.y;
    const int b  = bh >> 3;
    const int h  = bh & 7;
    const int q0 = qt * MQ;

    const float* qp = x + ((size_t)b * 3 * H_ * C_ + h * C_) * T_;
    float* op = out + ((size_t)b * H_ * C_ + h * C_) * T_;
    const uint32_t* KGp = KG + (size_t)bh * 65536;
    const uint32_t* VGp = VG + (size_t)bh * 65536;

    // ---- prologue: cp.async fp16 tile-pairs {0,1} and {2,3} (2 commit groups) ----
    #pragma unroll
    for (int pp = 0; pp < 2; pp++) {
        #pragma unroll
        for (int tt = 0; tt < 2; tt++) {
            int pf = 2 * pp + tt;
            uint32_t st = SB + (uint32_t)pf * STG_B;
            #pragma unroll
            for (int it = 0; it < 4; it++) {
                int idx = tid + it * NT;             // 1024 chunks
                int m   = idx >> 9;
                int ch  = (idx >> 3) & 63;
                int c8  = idx & 7;
                const uint32_t* src = (m ? VGp : KGp) + ch * 1024 + pf * 32 + c8 * 4;
                cp16(st + (uint32_t)m * V2REL + (uint32_t)ch * 144u + (uint32_t)c8 * 16u, src);
            }
        }
        CP_COMMIT();
    }

    // ---- Q fragments straight from gmem (contiguous 32B sectors per quad) ----
    uint32_t qa[2][4][4];
    #pragma unroll
    for (int mb = 0; mb < 2; mb++)
        #pragma unroll
        for (int kc = 0; kc < 4; kc++)
            #pragma unroll
            for (int j = 0; j < 4; j++) {
                int q = q0 + m0 + 16 * mb + lg + 8 * (j & 1);
                int c = kc * 8 + l4 + 4 * (j >> 1);          // channel-pair index
                const float* p = qp + (size_t)(2 * c) * T_ + q;
                float f0 = __ldg(p);
                float f1 = __ldg(p + T_);
                qa[mb][kc][j] = cvt2h(f1 * SCALE_LOG2, f0 * SCALE_LOG2);
            }

    float oc[2][8][4];
    float lsa[2][2] = {{0.f, 0.f}, {0.f, 0.f}};  // fp32 lsum partials
    #pragma unroll
    for (int mb = 0; mb < 2; mb++)
        #pragma unroll
        for (int nc = 0; nc < 8; nc++)
            #pragma unroll
            for (int e = 0; e < 4; e++) oc[mb][nc][e] = 0.f;

    // per-thread ldmatrix offsets within a stage
    const int jm = lid >> 3;
    const int rr = lid & 7;
    const uint32_t kof = (uint32_t)((8 * (jm & 1) + rr) * 144 + (jm >> 1) * 16);
    const uint32_t vof = V2REL + (uint32_t)(((jm >> 1) * 8 + rr) * 144 + (jm & 1) * 16);

    int stg = 0;                                 // stage of tile kt (kt % 6)

    #pragma unroll 1
    for (int kt = 0; kt < NTILES; kt++) {
        if ((kt & 1) == 0) {
            // issue cp.async for tiles kt+4, kt+5 into stages (kt+4)%6, (kt+5)%6
            // (those stages were consumed at tiles kt-2, kt-1 — all warps passed them
            //  before the barrier below on the PREVIOUS pair; and the new barrier
            //  below orders these fills' visibility for the pair after next)
            #pragma unroll
            for (int tt = 0; tt < 2; tt++) {
                int nt = kt + 4 + tt;
                if (nt < NTILES) {
                    int s = stg + 4 + tt; if (s >= 6) s -= 6;
                    uint32_t st = SB + (uint32_t)s * STG_B;
                    #pragma unroll
                    for (int it = 0; it < 4; it++) {
                        int idx = tid + it * NT;
                        int m   = idx >> 9;
                        int ch  = (idx >> 3) & 63;
                        int c8  = idx & 7;
                        const uint32_t* src = (m ? VGp : KGp) + ch * 1024 + nt * 32 + c8 * 4;
                        cp16(st + (uint32_t)m * V2REL + (uint32_t)ch * 144u + (uint32_t)c8 * 16u, src);
                    }
                }
            }
            CP_COMMIT();               // always commit (tail bookkeeping)
            CP_WAIT2();                // pair {kt, kt+1} landed (2 newer groups pending)
            __syncthreads();           // visibility + stage-reuse fence, once per pair
        }

        const uint32_t fb    = SB + (uint32_t)stg * STG_B;
        const uint32_t kbase = fb + kof;
        const uint32_t vbase = fb + vof;

        // ---- S = Q K^T ----
        float sc[2][8][4];
        #pragma unroll
        for (int mb = 0; mb < 2; mb++)
            #pragma unroll
            for (int nc = 0; nc < 8; nc++)
                #pragma unroll
                for (int e = 0; e < 4; e++) sc[mb][nc][e] = 0.f;

        #pragma unroll
        for (int ncp = 0; ncp < 4; ncp++) {
            #pragma unroll
            for (int kc = 0; kc < 4; kc++) {
                uint32_t f0, f1, f2, f3;
                LDSM4T(f0, f1, f2, f3, kbase + (uint32_t)(kc * 2304 + ncp * 32));
                mma16(sc[0][2 * ncp],     qa[0][kc], f0, f1);
                mma16(sc[1][2 * ncp],     qa[1][kc], f0, f1);
                mma16(sc[0][2 * ncp + 1], qa[0][kc], f2, f3);
                mma16(sc[1][2 * ncp + 1], qa[1][kc], f2, f3);
            }
        }

        // ---- softmax: pack logits to f16x2, exp2 both halves -> A fragments ----
        uint32_t pa[2][4][4];
        #pragma unroll
        for (int mb = 0; mb < 2; mb++) {
            #pragma unroll
            for (int kc = 0; kc < 4; kc++) {
                pa[mb][kc][0] = hex2(cvt2h(sc[mb][2 * kc][1],     sc[mb][2 * kc][0]));
                pa[mb][kc][1] = hex2(cvt2h(sc[mb][2 * kc][3],     sc[mb][2 * kc][2]));
                pa[mb][kc][2] = hex2(cvt2h(sc[mb][2 * kc + 1][1], sc[mb][2 * kc + 1][0]));
                pa[mb][kc][3] = hex2(cvt2h(sc[mb][2 * kc + 1][3], sc[mb][2 * kc + 1][2]));
            }
        }

        // ---- lsum via f16x2 adder tree (FMA pipe) ----
        #pragma unroll
        for (int mb = 0; mb < 2; mb++) {
            uint32_t r0 = hadd2(hadd2(pa[mb][0][0], pa[mb][1][0]),
                                hadd2(pa[mb][2][0], pa[mb][3][0]));
            uint32_t r2 = hadd2(hadd2(pa[mb][0][2], pa[mb][1][2]),
                                hadd2(pa[mb][2][2], pa[mb][3][2]));
            lsa[mb][0] += h2sum(hadd2(r0, r2));                 // row lg
            uint32_t r1 = hadd2(hadd2(pa[mb][0][1], pa[mb][1][1]),
                                hadd2(pa[mb][2][1], pa[mb][3][1]));
            uint32_t r3 = hadd2(hadd2(pa[mb][0][3], pa[mb][1][3]),
                                hadd2(pa[mb][2][3], pa[mb][3][3]));
            lsa[mb][1] += h2sum(hadd2(r1, r3));                 // row lg+8
        }

        // ---- O += P V^T ----
        #pragma unroll
        for (int ncp = 0; ncp < 4; ncp++) {
            #pragma unroll
            for (int kc = 0; kc < 4; kc++) {
                uint32_t f0, f1, f2, f3;
                LDSM4(f0, f1, f2, f3, vbase + (uint32_t)(ncp * 2304 + kc * 32));
                mma16(oc[0][2 * ncp],     pa[0][kc], f0, f1);
                mma16(oc[1][2 * ncp],     pa[1][kc], f0, f1);
                mma16(oc[0][2 * ncp + 1], pa[0][kc], f2, f3);
                mma16(oc[1][2 * ncp + 1], pa[1][kc], f2, f3);
            }
        }

        if (++stg == 6) stg = 0;
    }

    // ---- epilogue: quad-XOR reduces lsum over l4 lanes ----
    float inv[2][2];
    #pragma unroll
    for (int mb = 0; mb < 2; mb++) {
        float v0 = lsa[mb][0];
        float v1 = lsa[mb][1];
        v0 += __shfl_xor_sync(0xffffffffu, v0, 1);
        v0 += __shfl_xor_sync(0xffffffffu, v0, 2);
        v1 += __shfl_xor_sync(0xffffffffu, v1, 1);
        v1 += __shfl_xor_sync(0xffffffffu, v1, 2);
        inv[mb][0] = 1.0f / v0;
        inv[mb][1] = 1.0f / v1;
    }

    #pragma unroll
    for (int mb = 0; mb < 2; mb++) {
        int q = q0 + m0 + 16 * mb + lg;
        #pragma unroll
        for (int nc = 0; nc < 8; nc++) {
            int ch = 8 * nc + 2 * l4;
            op[(size_t)ch       * T_ + q]     = oc[mb][nc][0] * inv[mb][0];
            op[(size_t)(ch + 1) * T_ + q]     = oc[mb][nc][1] * inv[mb][0];
            op[(size_t)ch       * T_ + q + 8] = oc[mb][nc][2] * inv[mb][1];
            op[(size_t)(ch + 1) * T_ + q + 8] = oc[mb][nc][3] * inv[mb][1];
        }
    }
}

extern "C" void kernel_launch(void* const* d_in, const int* in_sizes, int n_in,
                              void* d_out, int out_size)
{
    const float* x   = (const float*)d_in[0];   // (4, 1536, 1024)
    const float* ekv = (const float*)d_in[1];   // (4, 1024, 1024)
    float* out = (float*)d_out;                 // (4, 512, 1024)

    prep_kernel<<<8192, 256>>>(x, ekv);

    cudaFuncSetAttribute(attn_r16_kernel, cudaFuncAttributeMaxDynamicSharedMemorySize, SMEM_BYTES);
    dim3 grid(T_ / MQ, B_ * H_);                // (4, 32) = 128 CTAs, 1/SM, one wave
    attn_r16_kernel<<<grid, NT, SMEM_BYTES>>>(x, out);
}